// round 2
// baseline (speedup 1.0000x reference)
#include <cuda_runtime.h>

// Problem constants
#define N_TOT   32768      // B*H*W
#define D_DIM   256
#define K_CODES 1024
#define HW_SZ   1024       // H*W
#define Q_ELEMS 8388608    // B*D*H*W
#define GATHER_BLOCKS 2048

// Device scratch (no runtime allocation allowed)
__device__ float g_enorm[K_CODES];
__device__ float g_xnorm[N_TOT];
__device__ int   g_idx[N_TOT];
__device__ float g_partials[GATHER_BLOCKS];
__device__ int   g_hist[K_CODES];

__device__ __forceinline__ float warpReduceSum(float v) {
    #pragma unroll
    for (int o = 16; o > 0; o >>= 1) v += __shfl_down_sync(0xffffffffu, v, o);
    return v;
}

// ---------------------------------------------------------------------------
// 1) ||e_k||^2 per code. grid=1024, block=256
// ---------------------------------------------------------------------------
__global__ void enorm_kernel(const float* __restrict__ emb) {
    __shared__ float red[8];
    int k = blockIdx.x;
    float v = emb[k * D_DIM + threadIdx.x];
    float s = v * v;
    s = warpReduceSum(s);
    if ((threadIdx.x & 31) == 0) red[threadIdx.x >> 5] = s;
    __syncthreads();
    if (threadIdx.x < 8) {
        float t = red[threadIdx.x];
        #pragma unroll
        for (int o = 4; o > 0; o >>= 1) t += __shfl_down_sync(0xffu, t, o);
        if (threadIdx.x == 0) g_enorm[k] = t;
    }
}

// ---------------------------------------------------------------------------
// 1b) ||x_n||^2 per row. One thread per n; adjacent threads = adjacent hw
//     -> coalesced strided reads. grid=128, block=256
// ---------------------------------------------------------------------------
__global__ void xnorm_kernel(const float* __restrict__ x) {
    int n = blockIdx.x * 256 + threadIdx.x;
    int b = n >> 10;
    int hw = n & 1023;
    const float* xb = x + ((size_t)b << 18) + hw;
    float acc = 0.f;
    #pragma unroll 8
    for (int d = 0; d < D_DIM; d++) {
        float v = xb[(size_t)d << 10];
        acc = fmaf(v, v, acc);
    }
    g_xnorm[n] = acc;
}

// ---------------------------------------------------------------------------
// 2) Fused distance GEMM + argmin, replicating reference rounding:
//      v = fl( fl(a_n + b_k) - 2*dot )   (all fp32)
//    Block tile: 128 rows x 128 codes, 8 code-tiles cover K=1024.
//    Thread micro-tile 8x8, D chunked by 16. grid=256, block=256 (16x16).
// ---------------------------------------------------------------------------
__global__ void __launch_bounds__(256, 2)
argmin_kernel(const float* __restrict__ x, const float* __restrict__ emb) {
    __shared__ __align__(16) float xs[16][128];
    __shared__ __align__(16) float es[16][132];   // pitch keeps rows 16B aligned
    __shared__ float en[K_CODES];
    __shared__ float rv[128][17];
    __shared__ int   ri[128][16];

    const int tid = threadIdx.x;
    const int tx = tid & 15;
    const int ty = tid >> 4;
    const int n0 = blockIdx.x << 7;      // 128 rows per block
    const int b  = n0 >> 10;             // HW=1024 rows per batch image
    const int hw0 = n0 & 1023;
    const float* xb = x + ((size_t)b << 18) + hw0;   // b * D*HW

    for (int i = tid; i < K_CODES; i += 256) en[i] = g_enorm[i];

    // per-thread row norms a_n for its 8 rows
    float arow[8];
    #pragma unroll
    for (int i = 0; i < 8; i++) arow[i] = g_xnorm[n0 + (ty << 3) + i];

    float bestv[8]; int besti[8];
    #pragma unroll
    for (int i = 0; i < 8; i++) { bestv[i] = 3.4e38f; besti[i] = 0; }

    for (int ct = 0; ct < 8; ct++) {
        float acc[8][8];
        #pragma unroll
        for (int i = 0; i < 8; i++)
            #pragma unroll
            for (int j = 0; j < 8; j++) acc[i][j] = 0.f;

        for (int dt = 0; dt < 16; dt++) {
            __syncthreads();
            const int d0 = dt << 4;
            #pragma unroll
            for (int i = 0; i < 8; i++) {
                int e  = tid + (i << 8);
                int r  = e & 127;
                int dc = e >> 7;
                xs[dc][r] = xb[((size_t)(d0 + dc) << 10) + r];
            }
            #pragma unroll
            for (int i = 0; i < 2; i++) {
                int v  = tid + (i << 8);       // 0..511
                int c  = v >> 2;               // code within tile (0..127)
                int dg = v & 3;                // group of 4 d's
                float4 t = *(const float4*)(emb + (((size_t)(ct << 7) + c) << 8) + d0 + (dg << 2));
                es[(dg << 2) + 0][c] = t.x;
                es[(dg << 2) + 1][c] = t.y;
                es[(dg << 2) + 2][c] = t.z;
                es[(dg << 2) + 3][c] = t.w;
            }
            __syncthreads();
            #pragma unroll
            for (int kk = 0; kk < 16; kk++) {
                float4 xa = *(const float4*)&xs[kk][ty << 3];
                float4 xc = *(const float4*)&xs[kk][(ty << 3) + 4];
                float4 ea = *(const float4*)&es[kk][tx << 3];
                float4 eb = *(const float4*)&es[kk][(tx << 3) + 4];
                float xr[8] = {xa.x, xa.y, xa.z, xa.w, xc.x, xc.y, xc.z, xc.w};
                float er[8] = {ea.x, ea.y, ea.z, ea.w, eb.x, eb.y, eb.z, eb.w};
                #pragma unroll
                for (int i = 0; i < 8; i++)
                    #pragma unroll
                    for (int j = 0; j < 8; j++)
                        acc[i][j] = fmaf(xr[i], er[j], acc[i][j]);
            }
        }
        // v = fl(fl(a + b_k) - 2*dot); running argmin (ascending k, strict <)
        #pragma unroll
        for (int j = 0; j < 8; j++) {
            int k = (ct << 7) + (tx << 3) + j;
            float enk = en[k];
            #pragma unroll
            for (int i = 0; i < 8; i++) {
                float s = arow[i] + enk;              // fl(a + b_k)
                float dist = fmaf(-2.f, acc[i][j], s); // fl(s - 2*dot)
                if (dist < bestv[i]) { bestv[i] = dist; besti[i] = k; }
            }
        }
    }

    __syncthreads();
    #pragma unroll
    for (int i = 0; i < 8; i++) {
        rv[(ty << 3) + i][tx] = bestv[i];
        ri[(ty << 3) + i][tx] = besti[i];
    }
    __syncthreads();
    if (tid < 128) {
        float bv = rv[tid][0]; int bi = ri[tid][0];
        #pragma unroll
        for (int t = 1; t < 16; t++) {
            float v = rv[tid][t]; int k = ri[tid][t];
            if (v < bv || (v == bv && k < bi)) { bv = v; bi = k; }
        }
        g_idx[n0 + tid] = bi;
    }
}

// ---------------------------------------------------------------------------
// 3) zero histogram. grid=4, block=256
// ---------------------------------------------------------------------------
__global__ void zero_hist_kernel() {
    int i = blockIdx.x * 256 + threadIdx.x;
    if (i < K_CODES) g_hist[i] = 0;
}

// ---------------------------------------------------------------------------
// 4) Gather quantized output + per-block SSE partials.
// ---------------------------------------------------------------------------
__global__ void gather_kernel(const float* __restrict__ x,
                              const float* __restrict__ emb,
                              float* __restrict__ out) {
    float sse = 0.f;
    const int total = Q_ELEMS / 4;   // 2097152
    for (int g = blockIdx.x * blockDim.x + threadIdx.x; g < total;
         g += gridDim.x * blockDim.x) {
        int hw4 = g & 255;
        int d   = (g >> 8) & 255;
        int b   = g >> 16;
        int n0  = (b << 10) + (hw4 << 2);
        float4 xv = ((const float4*)x)[g];
        float4 q;
        q.x = emb[(size_t)g_idx[n0 + 0] * D_DIM + d];
        q.y = emb[(size_t)g_idx[n0 + 1] * D_DIM + d];
        q.z = emb[(size_t)g_idx[n0 + 2] * D_DIM + d];
        q.w = emb[(size_t)g_idx[n0 + 3] * D_DIM + d];
        ((float4*)out)[g] = q;
        float a = q.x - xv.x, c = q.y - xv.y, e = q.z - xv.z, f = q.w - xv.w;
        sse += a * a + c * c + e * e + f * f;
    }
    __shared__ float red[8];
    sse = warpReduceSum(sse);
    if ((threadIdx.x & 31) == 0) red[threadIdx.x >> 5] = sse;
    __syncthreads();
    if (threadIdx.x < 8) {
        float v = red[threadIdx.x];
        #pragma unroll
        for (int o = 4; o > 0; o >>= 1) v += __shfl_down_sync(0xffu, v, o);
        if (threadIdx.x == 0) g_partials[blockIdx.x] = v;
    }
}

// ---------------------------------------------------------------------------
// 5) Histogram of indices. grid=32, block=256
// ---------------------------------------------------------------------------
__global__ void hist_kernel() {
    __shared__ int sh[K_CODES];
    int tid = threadIdx.x;
    for (int i = tid; i < K_CODES; i += 256) sh[i] = 0;
    __syncthreads();
    int base = blockIdx.x * 1024;
    for (int i = tid; i < 1024; i += 256) atomicAdd(&sh[g_idx[base + i]], 1);
    __syncthreads();
    for (int i = tid; i < K_CODES; i += 256)
        if (sh[i]) atomicAdd(&g_hist[i], sh[i]);
}

// ---------------------------------------------------------------------------
// 6) Finalize: loss + perplexity. grid=1, block=1024
// ---------------------------------------------------------------------------
__global__ void finalize_kernel(float* __restrict__ out, int out_size) {
    __shared__ float red[32];
    int tid = threadIdx.x;
    float s = 0.f;
    for (int i = tid; i < GATHER_BLOCKS; i += 1024) s += g_partials[i];
    s = warpReduceSum(s);
    if ((tid & 31) == 0) red[tid >> 5] = s;
    __syncthreads();
    if (tid < 32) {
        float v = red[tid];
        v = warpReduceSum(v);
        if (tid == 0 && out_size > Q_ELEMS)
            out[Q_ELEMS] = 1.25f * v / (float)Q_ELEMS;   // q_latent + 0.25*e_latent
    }
    __syncthreads();
    float p = (float)g_hist[tid] / (float)N_TOT;
    float t = -p * logf(p + 1e-10f);
    t = warpReduceSum(t);
    if ((tid & 31) == 0) red[tid >> 5] = t;
    __syncthreads();
    if (tid < 32) {
        float v = red[tid];
        v = warpReduceSum(v);
        if (tid == 0 && out_size > Q_ELEMS + 1)
            out[Q_ELEMS + 1] = expf(v);
    }
}

// ---------------------------------------------------------------------------
// 7) Indices as float (if the output buffer includes them). grid=128, block=256
// ---------------------------------------------------------------------------
__global__ void idx_out_kernel(float* __restrict__ out) {
    int i = blockIdx.x * 256 + threadIdx.x;
    if (i < N_TOT) out[Q_ELEMS + 2 + i] = (float)g_idx[i];
}

// ---------------------------------------------------------------------------
extern "C" void kernel_launch(void* const* d_in, const int* in_sizes, int n_in,
                              void* d_out, int out_size) {
    const float* inputs = (const float*)d_in[0];
    const float* emb    = (const float*)d_in[1];
    if (n_in >= 2 && in_sizes[0] == K_CODES * D_DIM && in_sizes[1] == Q_ELEMS) {
        const float* t = inputs; inputs = emb; emb = t;
    }
    float* out = (float*)d_out;

    enorm_kernel<<<K_CODES, 256>>>(emb);
    xnorm_kernel<<<N_TOT / 256, 256>>>(inputs);
    argmin_kernel<<<N_TOT / 128, 256>>>(inputs, emb);
    zero_hist_kernel<<<4, 256>>>();
    gather_kernel<<<GATHER_BLOCKS, 256>>>(inputs, emb, out);
    hist_kernel<<<32, 256>>>();
    finalize_kernel<<<1, 1024>>>(out, out_size);
    if (out_size >= Q_ELEMS + 2 + N_TOT) {
        idx_out_kernel<<<128, 256>>>(out);
    }
}

// round 3
// speedup vs baseline: 1.0140x; 1.0140x over previous
#include <cuda_runtime.h>

// Problem constants
#define N_TOT   32768      // B*H*W
#define D_DIM   256
#define K_CODES 1024
#define HW_SZ   1024       // H*W
#define Q_ELEMS 8388608    // B*D*H*W
#define GATHER_BLOCKS 2048

// Device scratch (no runtime allocation allowed)
__device__ float g_enorm[K_CODES];
__device__ int   g_idx[N_TOT];
__device__ float g_partials[GATHER_BLOCKS];
__device__ int   g_hist[K_CODES];

typedef unsigned long long u64;

__device__ __forceinline__ float warpReduceSum(float v) {
    #pragma unroll
    for (int o = 16; o > 0; o >>= 1) v += __shfl_down_sync(0xffffffffu, v, o);
    return v;
}

// Packed f32x2 FMA (Blackwell; ptxas never auto-emits this)
#define FMA2(d, a, b, c) \
    asm("fma.rn.f32x2 %0, %1, %2, %3;" : "=l"(d) : "l"(a), "l"(b), "l"(c))

__device__ __forceinline__ u64 bc2(float v) {
    unsigned int u = __float_as_uint(v);
    u64 r;
    asm("mov.b64 %0, {%1, %1};" : "=l"(r) : "r"(u));
    return r;
}
__device__ __forceinline__ void unpack2(u64 v, float& lo, float& hi) {
    unsigned int a, b;
    asm("mov.b64 {%0, %1}, %2;" : "=r"(a), "=r"(b) : "l"(v));
    lo = __uint_as_float(a);
    hi = __uint_as_float(b);
}

// ---------------------------------------------------------------------------
// 1) ||e_k||^2 per code. grid=1024, block=256
// ---------------------------------------------------------------------------
__global__ void enorm_kernel(const float* __restrict__ emb) {
    __shared__ float red[8];
    int k = blockIdx.x;
    float v = emb[k * D_DIM + threadIdx.x];
    float s = v * v;
    s = warpReduceSum(s);
    if ((threadIdx.x & 31) == 0) red[threadIdx.x >> 5] = s;
    __syncthreads();
    if (threadIdx.x < 8) {
        float t = red[threadIdx.x];
        #pragma unroll
        for (int o = 4; o > 0; o >>= 1) t += __shfl_down_sync(0xffu, t, o);
        if (threadIdx.x == 0) g_enorm[k] = t;
    }
}

// ---------------------------------------------------------------------------
// 2) Fused distance GEMM + argmin with packed f32x2 FMAs.
//    Block tile: 128 rows x 128 codes, 8 code-tiles cover K=1024.
//    Thread micro-tile: 4 row-pairs x 8 codes. grid=256, block=256 (16x16).
//    ||x||^2 computed in-pass during ct=0.
//    dist = fl( fl(a_n + b_k) - 2*dot )  replicates reference rounding.
// ---------------------------------------------------------------------------
__global__ void __launch_bounds__(256, 2)
argmin_kernel(const float* __restrict__ x, const float* __restrict__ emb) {
    __shared__ __align__(16) float xs[16][128];
    __shared__ __align__(16) float es[16][132];   // pitch 132: rows stay 16B aligned
    __shared__ float en[K_CODES];
    __shared__ float rv[128][17];
    __shared__ int   ri[128][16];

    const int tid = threadIdx.x;
    const int tx = tid & 15;
    const int ty = tid >> 4;
    const int n0 = blockIdx.x << 7;      // 128 rows per block
    const int b  = n0 >> 10;
    const int hw0 = n0 & 1023;
    const float* xb = x + ((size_t)b << 18) + hw0;   // b * D*HW

    for (int i = tid; i < K_CODES; i += 256) en[i] = g_enorm[i];

    float bestv[8]; int besti[8];
    #pragma unroll
    for (int i = 0; i < 8; i++) { bestv[i] = 3.4e38f; besti[i] = 0; }

    float arow[8];
    u64 xn2[4];
    #pragma unroll
    for (int p = 0; p < 4; p++) xn2[p] = 0ull;

    for (int ct = 0; ct < 8; ct++) {
        u64 acc2[4][8];
        #pragma unroll
        for (int p = 0; p < 4; p++)
            #pragma unroll
            for (int j = 0; j < 8; j++) acc2[p][j] = 0ull;

        for (int dt = 0; dt < 16; dt++) {
            __syncthreads();
            const int d0 = dt << 4;
            // load xs[dc][r]: coalesced 128-wide per d-column
            #pragma unroll
            for (int i = 0; i < 8; i++) {
                int e  = tid + (i << 8);
                int r  = e & 127;
                int dc = e >> 7;
                xs[dc][r] = xb[((size_t)(d0 + dc) << 10) + r];
            }
            // load es from row-major emb via float4 (coalesced)
            #pragma unroll
            for (int i = 0; i < 2; i++) {
                int v  = tid + (i << 8);       // 0..511
                int c  = v >> 2;               // code within tile (0..127)
                int dg = v & 3;                // group of 4 d's
                float4 t = *(const float4*)(emb + (((size_t)(ct << 7) + c) << 8) + d0 + (dg << 2));
                es[(dg << 2) + 0][c] = t.x;
                es[(dg << 2) + 1][c] = t.y;
                es[(dg << 2) + 2][c] = t.z;
                es[(dg << 2) + 3][c] = t.w;
            }
            __syncthreads();
            if (ct == 0) {
                #pragma unroll
                for (int kk = 0; kk < 16; kk++) {
                    const u64* xp = (const u64*)&xs[kk][ty << 3];
                    u64 x2[4] = {xp[0], xp[1], xp[2], xp[3]};
                    float4 ea = *(const float4*)&es[kk][tx << 3];
                    float4 eb = *(const float4*)&es[kk][(tx << 3) + 4];
                    u64 eB[8] = {bc2(ea.x), bc2(ea.y), bc2(ea.z), bc2(ea.w),
                                 bc2(eb.x), bc2(eb.y), bc2(eb.z), bc2(eb.w)};
                    #pragma unroll
                    for (int p = 0; p < 4; p++) {
                        FMA2(xn2[p], x2[p], x2[p], xn2[p]);   // row-norm accumulate
                        #pragma unroll
                        for (int j = 0; j < 8; j++)
                            FMA2(acc2[p][j], x2[p], eB[j], acc2[p][j]);
                    }
                }
            } else {
                #pragma unroll
                for (int kk = 0; kk < 16; kk++) {
                    const u64* xp = (const u64*)&xs[kk][ty << 3];
                    u64 x2[4] = {xp[0], xp[1], xp[2], xp[3]};
                    float4 ea = *(const float4*)&es[kk][tx << 3];
                    float4 eb = *(const float4*)&es[kk][(tx << 3) + 4];
                    u64 eB[8] = {bc2(ea.x), bc2(ea.y), bc2(ea.z), bc2(ea.w),
                                 bc2(eb.x), bc2(eb.y), bc2(eb.z), bc2(eb.w)};
                    #pragma unroll
                    for (int p = 0; p < 4; p++)
                        #pragma unroll
                        for (int j = 0; j < 8; j++)
                            FMA2(acc2[p][j], x2[p], eB[j], acc2[p][j]);
                }
            }
        }
        if (ct == 0) {
            #pragma unroll
            for (int p = 0; p < 4; p++)
                unpack2(xn2[p], arow[2 * p], arow[2 * p + 1]);
        }
        // dist epilogue + running argmin (ascending k, strict < keeps earliest)
        #pragma unroll
        for (int j = 0; j < 8; j++) {
            int k = (ct << 7) + (tx << 3) + j;
            float enk = en[k];
            #pragma unroll
            for (int p = 0; p < 4; p++) {
                float dlo, dhi;
                unpack2(acc2[p][j], dlo, dhi);
                {
                    float s = arow[2 * p] + enk;
                    float dist = fmaf(-2.f, dlo, s);
                    if (dist < bestv[2 * p]) { bestv[2 * p] = dist; besti[2 * p] = k; }
                }
                {
                    float s = arow[2 * p + 1] + enk;
                    float dist = fmaf(-2.f, dhi, s);
                    if (dist < bestv[2 * p + 1]) { bestv[2 * p + 1] = dist; besti[2 * p + 1] = k; }
                }
            }
        }
    }

    __syncthreads();
    #pragma unroll
    for (int i = 0; i < 8; i++) {
        rv[(ty << 3) + i][tx] = bestv[i];
        ri[(ty << 3) + i][tx] = besti[i];
    }
    __syncthreads();
    if (tid < 128) {
        float bv = rv[tid][0]; int bi = ri[tid][0];
        #pragma unroll
        for (int t = 1; t < 16; t++) {
            float v = rv[tid][t]; int k = ri[tid][t];
            if (v < bv || (v == bv && k < bi)) { bv = v; bi = k; }
        }
        g_idx[n0 + tid] = bi;
    }
}

// ---------------------------------------------------------------------------
// 3) zero histogram. grid=4, block=256
// ---------------------------------------------------------------------------
__global__ void zero_hist_kernel() {
    int i = blockIdx.x * 256 + threadIdx.x;
    if (i < K_CODES) g_hist[i] = 0;
}

// ---------------------------------------------------------------------------
// 4) Gather quantized output + per-block SSE partials.
// ---------------------------------------------------------------------------
__global__ void gather_kernel(const float* __restrict__ x,
                              const float* __restrict__ emb,
                              float* __restrict__ out) {
    float sse = 0.f;
    const int total = Q_ELEMS / 4;   // 2097152
    for (int g = blockIdx.x * blockDim.x + threadIdx.x; g < total;
         g += gridDim.x * blockDim.x) {
        int hw4 = g & 255;
        int d   = (g >> 8) & 255;
        int b   = g >> 16;
        int n0  = (b << 10) + (hw4 << 2);
        float4 xv = ((const float4*)x)[g];
        float4 q;
        q.x = emb[(size_t)g_idx[n0 + 0] * D_DIM + d];
        q.y = emb[(size_t)g_idx[n0 + 1] * D_DIM + d];
        q.z = emb[(size_t)g_idx[n0 + 2] * D_DIM + d];
        q.w = emb[(size_t)g_idx[n0 + 3] * D_DIM + d];
        ((float4*)out)[g] = q;
        float a = q.x - xv.x, c = q.y - xv.y, e = q.z - xv.z, f = q.w - xv.w;
        sse += a * a + c * c + e * e + f * f;
    }
    __shared__ float red[8];
    sse = warpReduceSum(sse);
    if ((threadIdx.x & 31) == 0) red[threadIdx.x >> 5] = sse;
    __syncthreads();
    if (threadIdx.x < 8) {
        float v = red[threadIdx.x];
        #pragma unroll
        for (int o = 4; o > 0; o >>= 1) v += __shfl_down_sync(0xffu, v, o);
        if (threadIdx.x == 0) g_partials[blockIdx.x] = v;
    }
}

// ---------------------------------------------------------------------------
// 5) Histogram of indices. grid=32, block=256
// ---------------------------------------------------------------------------
__global__ void hist_kernel() {
    __shared__ int sh[K_CODES];
    int tid = threadIdx.x;
    for (int i = tid; i < K_CODES; i += 256) sh[i] = 0;
    __syncthreads();
    int base = blockIdx.x * 1024;
    for (int i = tid; i < 1024; i += 256) atomicAdd(&sh[g_idx[base + i]], 1);
    __syncthreads();
    for (int i = tid; i < K_CODES; i += 256)
        if (sh[i]) atomicAdd(&g_hist[i], sh[i]);
}

// ---------------------------------------------------------------------------
// 6) Finalize: loss + perplexity. grid=1, block=1024
// ---------------------------------------------------------------------------
__global__ void finalize_kernel(float* __restrict__ out, int out_size) {
    __shared__ float red[32];
    int tid = threadIdx.x;
    float s = 0.f;
    for (int i = tid; i < GATHER_BLOCKS; i += 1024) s += g_partials[i];
    s = warpReduceSum(s);
    if ((tid & 31) == 0) red[tid >> 5] = s;
    __syncthreads();
    if (tid < 32) {
        float v = red[tid];
        v = warpReduceSum(v);
        if (tid == 0 && out_size > Q_ELEMS)
            out[Q_ELEMS] = 1.25f * v / (float)Q_ELEMS;   // q_latent + 0.25*e_latent
    }
    __syncthreads();
    float p = (float)g_hist[tid] / (float)N_TOT;
    float t = -p * logf(p + 1e-10f);
    t = warpReduceSum(t);
    if ((tid & 31) == 0) red[tid >> 5] = t;
    __syncthreads();
    if (tid < 32) {
        float v = red[tid];
        v = warpReduceSum(v);
        if (tid == 0 && out_size > Q_ELEMS + 1)
            out[Q_ELEMS + 1] = expf(v);
    }
}

// ---------------------------------------------------------------------------
// 7) Indices as float (if the output buffer includes them). grid=128, block=256
// ---------------------------------------------------------------------------
__global__ void idx_out_kernel(float* __restrict__ out) {
    int i = blockIdx.x * 256 + threadIdx.x;
    if (i < N_TOT) out[Q_ELEMS + 2 + i] = (float)g_idx[i];
}

// ---------------------------------------------------------------------------
extern "C" void kernel_launch(void* const* d_in, const int* in_sizes, int n_in,
                              void* d_out, int out_size) {
    const float* inputs = (const float*)d_in[0];
    const float* emb    = (const float*)d_in[1];
    if (n_in >= 2 && in_sizes[0] == K_CODES * D_DIM && in_sizes[1] == Q_ELEMS) {
        const float* t = inputs; inputs = emb; emb = t;
    }
    float* out = (float*)d_out;

    enorm_kernel<<<K_CODES, 256>>>(emb);
    argmin_kernel<<<N_TOT / 128, 256>>>(inputs, emb);
    zero_hist_kernel<<<4, 256>>>();
    gather_kernel<<<GATHER_BLOCKS, 256>>>(inputs, emb, out);
    hist_kernel<<<32, 256>>>();
    finalize_kernel<<<1, 1024>>>(out, out_size);
    if (out_size >= Q_ELEMS + 2 + N_TOT) {
        idx_out_kernel<<<128, 256>>>(out);
    }
}

// round 5
// speedup vs baseline: 1.7774x; 1.7528x over previous
#include <cuda_runtime.h>

// Problem constants
#define N_TOT   32768      // B*H*W
#define D_DIM   256
#define K_CODES 1024
#define Q_ELEMS 8388608    // B*D*H*W
#define GATHER_BLOCKS 2048

#define XS_PITCH 136       // (8k + r) % 32 distinct -> conflict-free A-frag loads
#define ES_PITCH 260       // 260 % 32 == 4 -> (4c + k) distinct -> conflict-free B loads
#define NC_CODES 64        // codes per e-chunk
#define NUM_NC   (K_CODES / NC_CODES)
#define TAU      2e-4f

// Device scratch (no runtime allocation allowed)
__device__ float g_enorm[K_CODES];
__device__ int   g_idx[N_TOT];
__device__ int   g_ncand[N_TOT];
__device__ float g_cand_v[N_TOT][16];
__device__ int   g_cand_i[N_TOT][16];
__device__ float g_partials[GATHER_BLOCKS];
__device__ int   g_hist[K_CODES];

__device__ __forceinline__ float warpReduceSum(float v) {
    #pragma unroll
    for (int o = 16; o > 0; o >>= 1) v += __shfl_down_sync(0xffffffffu, v, o);
    return v;
}

__device__ __forceinline__ unsigned tf32h(float x) {
    unsigned r;
    asm("cvt.rna.tf32.f32 %0, %1;" : "=r"(r) : "f"(x));
    return r;
}

#define MMA_TF32(c0,c1,c2,c3, a0,a1,a2,a3, b0,b1)                              \
    asm volatile("mma.sync.aligned.m16n8k8.row.col.f32.tf32.tf32.f32 "         \
                 "{%0,%1,%2,%3},{%4,%5,%6,%7},{%8,%9},{%0,%1,%2,%3};"          \
                 : "+f"(c0), "+f"(c1), "+f"(c2), "+f"(c3)                      \
                 : "r"(a0), "r"(a1), "r"(a2), "r"(a3), "r"(b0), "r"(b1))

// ---------------------------------------------------------------------------
// 1) ||e_k||^2 per code. grid=1024, block=256
// ---------------------------------------------------------------------------
__global__ void enorm_kernel(const float* __restrict__ emb) {
    __shared__ float red[8];
    int k = blockIdx.x;
    float v = emb[k * D_DIM + threadIdx.x];
    float s = v * v;
    s = warpReduceSum(s);
    if ((threadIdx.x & 31) == 0) red[threadIdx.x >> 5] = s;
    __syncthreads();
    if (threadIdx.x < 8) {
        float t = red[threadIdx.x];
        #pragma unroll
        for (int o = 4; o > 0; o >>= 1) t += __shfl_down_sync(0xffu, t, o);
        if (threadIdx.x == 0) g_enorm[k] = t;
    }
}

// ---------------------------------------------------------------------------
// 2) Approx distance GEMM (single tf32 MMA) + per-lane best-2 + candidate emit.
//    CTA: 128 rows x 1024 codes. 8 warps = 4 row-groups(32) x 2 code-halves.
//    grid=256, block=256, dyn smem ~210KB, 1 CTA/SM.
// ---------------------------------------------------------------------------
__global__ void __launch_bounds__(256, 1)
argmin_mma_kernel(const float* __restrict__ x, const float* __restrict__ emb) {
    extern __shared__ float sm[];
    float*    xs    = sm;                                  // [256][XS_PITCH] fp32, d-major
    unsigned* es    = (unsigned*)(xs + 256 * XS_PITCH);    // [64][ES_PITCH] tf32, code-major
    float*    en_s  = (float*)(es + NC_CODES * ES_PITCH);  // [1024]
    float*    norms = en_s + K_CODES;                      // [128]
    // candidate buffers alias es after the main loop
    float* cand_v = (float*)es;                // [128][16]
    int*   cand_i = (int*)(cand_v + 128 * 16); // [128][16]

    const int tid  = threadIdx.x;
    const int lane = tid & 31;
    const int w    = tid >> 5;
    const int g4   = lane >> 2;
    const int tg   = lane & 3;
    const int rg   = w & 3;        // row group (32 rows)
    const int ch   = w >> 2;       // code half within chunk
    const int wr0  = rg << 5;
    const int n0   = blockIdx.x << 7;
    const int b    = n0 >> 10;
    const int hw0  = n0 & 1023;
    const float* xb = x + ((size_t)b << 18) + hw0;

    // Load x tile: 128 rows x 256 d (coalesced over contiguous hw)
    #pragma unroll
    for (int i = 0; i < 32; i++) {
        int v  = tid + (i << 8);
        int d  = v >> 5;
        int r4 = (v & 31) << 2;
        float4 t = *(const float4*)(xb + ((size_t)d << 10) + r4);
        *(float4*)&xs[d * XS_PITCH + r4] = t;
    }
    for (int i = tid; i < K_CODES; i += 256) en_s[i] = g_enorm[i];
    __syncthreads();

    // Row norms (exact fp32, per-row; es used as scratch before staging)
    {
        int row = tid & 127;
        int h   = tid >> 7;
        float a = 0.f;
        const float* p = &xs[(h << 7) * XS_PITCH + row];
        #pragma unroll 8
        for (int d = 0; d < 128; d++) {
            float v = p[d * XS_PITCH];
            a = fmaf(v, v, a);
        }
        ((float*)es)[tid] = a;
    }
    __syncthreads();
    if (tid < 128) norms[tid] = ((float*)es)[tid] + ((float*)es)[tid + 128];
    __syncthreads();

    float na[4];
    #pragma unroll
    for (int q = 0; q < 4; q++) na[q] = norms[wr0 + g4 + (q << 3)];

    // per-lane best-2 (lexicographic on value,index) for rows wr0+g4+8q
    float bv[4][2]; int bi[4][2];
    #pragma unroll
    for (int q = 0; q < 4; q++) {
        bv[q][0] = 3.4e38f; bv[q][1] = 3.4e38f;
        bi[q][0] = 0x7fffffff; bi[q][1] = 0x7fffffff;
    }

    for (int cc = 0; cc < NUM_NC; cc++) {
        __syncthreads();
        const int k0c = cc << 6;
        // Stage 64 codes x 256 d as tf32, code-major [c][ES_PITCH]
        #pragma unroll
        for (int i = 0; i < 16; i++) {
            int v  = tid + (i << 8);        // 0..4095
            int c  = v >> 6;                // code 0..63
            int d4 = (v & 63) << 2;
            float4 t = *(const float4*)(emb + (((size_t)(k0c + c)) << 8) + d4);
            uint4 u;
            u.x = tf32h(t.x); u.y = tf32h(t.y); u.z = tf32h(t.z); u.w = tf32h(t.w);
            *(uint4*)&es[c * ES_PITCH + d4] = u;
        }
        __syncthreads();

        float acc[2][4][4];   // [m-block][s][cfrag]
        #pragma unroll
        for (int m = 0; m < 2; m++)
            #pragma unroll
            for (int s = 0; s < 4; s++)
                #pragma unroll
                for (int j = 0; j < 4; j++) acc[m][s][j] = 0.f;

        for (int kt = 0; kt < 32; kt++) {
            const int k0 = kt << 3;
            unsigned a_[2][4];
            #pragma unroll
            for (int m = 0; m < 2; m++) {
                int r0 = wr0 + (m << 4) + g4;
                a_[m][0] = tf32h(xs[(k0 + tg) * XS_PITCH + r0]);
                a_[m][1] = tf32h(xs[(k0 + tg) * XS_PITCH + r0 + 8]);
                a_[m][2] = tf32h(xs[(k0 + tg + 4) * XS_PITCH + r0]);
                a_[m][3] = tf32h(xs[(k0 + tg + 4) * XS_PITCH + r0 + 8]);
            }
            #pragma unroll
            for (int s = 0; s < 4; s++) {
                int cl = (ch << 5) + (s << 3) + g4;   // code within chunk
                unsigned b0 = es[cl * ES_PITCH + k0 + tg];
                unsigned b1 = es[cl * ES_PITCH + k0 + tg + 4];
                MMA_TF32(acc[0][s][0], acc[0][s][1], acc[0][s][2], acc[0][s][3],
                         a_[0][0], a_[0][1], a_[0][2], a_[0][3], b0, b1);
                MMA_TF32(acc[1][s][0], acc[1][s][1], acc[1][s][2], acc[1][s][3],
                         a_[1][0], a_[1][1], a_[1][2], a_[1][3], b0, b1);
            }
        }
        // Epilogue: approx dist + best-2 insert
        #pragma unroll
        for (int s = 0; s < 4; s++) {
            int kb = k0c + (ch << 5) + (s << 3) + (tg << 1);
            float e0 = en_s[kb], e1 = en_s[kb + 1];
            #pragma unroll
            for (int m = 0; m < 2; m++) {
                #pragma unroll
                for (int half = 0; half < 2; half++) {
                    int q = (m << 1) + half;
                    float base = na[q];
                    float d0 = fmaf(-2.f, acc[m][s][(half << 1)], base + e0);
                    float d1 = fmaf(-2.f, acc[m][s][(half << 1) + 1], base + e1);
                    // insert (d0, kb)
                    if (d0 < bv[q][1] || (d0 == bv[q][1] && kb < bi[q][1])) {
                        bv[q][1] = d0; bi[q][1] = kb;
                        if (bv[q][1] < bv[q][0] ||
                            (bv[q][1] == bv[q][0] && bi[q][1] < bi[q][0])) {
                            float tv = bv[q][0]; bv[q][0] = bv[q][1]; bv[q][1] = tv;
                            int   ti = bi[q][0]; bi[q][0] = bi[q][1]; bi[q][1] = ti;
                        }
                    }
                    // insert (d1, kb+1)
                    int k1 = kb + 1;
                    if (d1 < bv[q][1] || (d1 == bv[q][1] && k1 < bi[q][1])) {
                        bv[q][1] = d1; bi[q][1] = k1;
                        if (bv[q][1] < bv[q][0] ||
                            (bv[q][1] == bv[q][0] && bi[q][1] < bi[q][0])) {
                            float tv = bv[q][0]; bv[q][0] = bv[q][1]; bv[q][1] = tv;
                            int   ti = bi[q][0]; bi[q][0] = bi[q][1]; bi[q][1] = ti;
                        }
                    }
                }
            }
        }
    }

    __syncthreads();   // everyone done reading es -> safe to alias as cand buffers

    // Gather 4 lanes' best-2 per row into cand[row][ch*8 .. ch*8+7]
    const int gbase = lane & ~3;
    #pragma unroll
    for (int q = 0; q < 4; q++) {
        int row = wr0 + g4 + (q << 3);
        int off = row * 16 + (ch << 3);
        #pragma unroll
        for (int s = 0; s < 4; s++) {
            float gv1 = __shfl_sync(0xffffffffu, bv[q][0], gbase + s);
            int   gi1 = __shfl_sync(0xffffffffu, bi[q][0], gbase + s);
            float gv2 = __shfl_sync(0xffffffffu, bv[q][1], gbase + s);
            int   gi2 = __shfl_sync(0xffffffffu, bi[q][1], gbase + s);
            if (tg == 0) {
                cand_v[off + 2 * s]     = gv1;  cand_i[off + 2 * s]     = gi1;
                cand_v[off + 2 * s + 1] = gv2;  cand_i[off + 2 * s + 1] = gi2;
            }
        }
    }
    __syncthreads();

    // Final decision per row
    if (tid < 128) {
        int row = tid;
        float vm = cand_v[row * 16]; int im = cand_i[row * 16];
        #pragma unroll
        for (int j = 1; j < 16; j++) {
            float v = cand_v[row * 16 + j]; int k = cand_i[row * 16 + j];
            if (v < vm || (v == vm && k < im)) { vm = v; im = k; }
        }
        int cnt = 0;
        #pragma unroll
        for (int j = 0; j < 16; j++) cnt += (cand_v[row * 16 + j] <= vm + TAU);
        int n = n0 + row;
        if (cnt == 1) {
            g_idx[n] = im;
            g_ncand[n] = 1;
        } else {
            g_ncand[n] = 16;
            #pragma unroll
            for (int j = 0; j < 16; j++) {
                g_cand_v[n][j] = cand_v[row * 16 + j];
                g_cand_i[n][j] = cand_i[row * 16 + j];
            }
        }
    }
}

// ---------------------------------------------------------------------------
// 2b) Exact rescore of flagged rows (one warp per row). grid=4096, block=256
// ---------------------------------------------------------------------------
__global__ void rescore_kernel(const float* __restrict__ x,
                               const float* __restrict__ emb) {
    int wid  = (blockIdx.x * blockDim.x + threadIdx.x) >> 5;
    int lane = threadIdx.x & 31;
    if (wid >= N_TOT) return;
    if (g_ncand[wid] == 1) return;

    int b = wid >> 10, hw = wid & 1023;
    const float* xr = x + ((size_t)b << 18) + hw;
    float xv[8];
    #pragma unroll
    for (int t = 0; t < 8; t++) xv[t] = xr[(size_t)(lane + (t << 5)) << 10];
    float a = 0.f;
    #pragma unroll
    for (int t = 0; t < 8; t++) a = fmaf(xv[t], xv[t], a);
    #pragma unroll
    for (int o = 16; o > 0; o >>= 1) a += __shfl_xor_sync(0xffffffffu, a, o);

    float cv[16]; int ci[16];
    #pragma unroll
    for (int j = 0; j < 16; j++) { cv[j] = g_cand_v[wid][j]; ci[j] = g_cand_i[wid][j]; }
    float vmin = cv[0];
    #pragma unroll
    for (int j = 1; j < 16; j++) vmin = fminf(vmin, cv[j]);

    float bestv = 3.4e38f; int besti = 0x7fffffff;
    for (int j = 0; j < 16; j++) {
        if (cv[j] > vmin + TAU) continue;
        int k = ci[j];
        const float* er = emb + ((size_t)k << 8);
        float d = 0.f;
        #pragma unroll
        for (int t = 0; t < 8; t++) d = fmaf(xv[t], er[lane + (t << 5)], d);
        #pragma unroll
        for (int o = 16; o > 0; o >>= 1) d += __shfl_xor_sync(0xffffffffu, d, o);
        float vv = fmaf(-2.f, d, a + g_enorm[k]);   // fl(fl(a+b) - 2*dot)
        if (vv < bestv || (vv == bestv && k < besti)) { bestv = vv; besti = k; }
    }
    if (lane == 0) g_idx[wid] = besti;
}

// ---------------------------------------------------------------------------
// 3) zero histogram. grid=4, block=256
// ---------------------------------------------------------------------------
__global__ void zero_hist_kernel() {
    int i = blockIdx.x * 256 + threadIdx.x;
    if (i < K_CODES) g_hist[i] = 0;
}

// ---------------------------------------------------------------------------
// 4) Gather quantized output + per-block SSE partials.
// ---------------------------------------------------------------------------
__global__ void gather_kernel(const float* __restrict__ x,
                              const float* __restrict__ emb,
                              float* __restrict__ out) {
    float sse = 0.f;
    const int total = Q_ELEMS / 4;   // 2097152
    for (int g = blockIdx.x * blockDim.x + threadIdx.x; g < total;
         g += gridDim.x * blockDim.x) {
        int hw4 = g & 255;
        int d   = (g >> 8) & 255;
        int b   = g >> 16;
        int n0  = (b << 10) + (hw4 << 2);
        float4 xv = ((const float4*)x)[g];
        float4 q;
        q.x = emb[(size_t)g_idx[n0 + 0] * D_DIM + d];
        q.y = emb[(size_t)g_idx[n0 + 1] * D_DIM + d];
        q.z = emb[(size_t)g_idx[n0 + 2] * D_DIM + d];
        q.w = emb[(size_t)g_idx[n0 + 3] * D_DIM + d];
        ((float4*)out)[g] = q;
        float a = q.x - xv.x, c = q.y - xv.y, e = q.z - xv.z, f = q.w - xv.w;
        sse += a * a + c * c + e * e + f * f;
    }
    __shared__ float red[8];
    sse = warpReduceSum(sse);
    if ((threadIdx.x & 31) == 0) red[threadIdx.x >> 5] = sse;
    __syncthreads();
    if (threadIdx.x < 8) {
        float v = red[threadIdx.x];
        #pragma unroll
        for (int o = 4; o > 0; o >>= 1) v += __shfl_down_sync(0xffu, v, o);
        if (threadIdx.x == 0) g_partials[blockIdx.x] = v;
    }
}

// ---------------------------------------------------------------------------
// 5) Histogram of indices. grid=32, block=256
// ---------------------------------------------------------------------------
__global__ void hist_kernel() {
    __shared__ int sh[K_CODES];
    int tid = threadIdx.x;
    for (int i = tid; i < K_CODES; i += 256) sh[i] = 0;
    __syncthreads();
    int base = blockIdx.x * 1024;
    for (int i = tid; i < 1024; i += 256) atomicAdd(&sh[g_idx[base + i]], 1);
    __syncthreads();
    for (int i = tid; i < K_CODES; i += 256)
        if (sh[i]) atomicAdd(&g_hist[i], sh[i]);
}

// ---------------------------------------------------------------------------
// 6) Finalize: loss + perplexity. grid=1, block=1024
// ---------------------------------------------------------------------------
__global__ void finalize_kernel(float* __restrict__ out, int out_size) {
    __shared__ float red[32];
    int tid = threadIdx.x;
    float s = 0.f;
    for (int i = tid; i < GATHER_BLOCKS; i += 1024) s += g_partials[i];
    s = warpReduceSum(s);
    if ((tid & 31) == 0) red[tid >> 5] = s;
    __syncthreads();
    if (tid < 32) {
        float v = red[tid];
        v = warpReduceSum(v);
        if (tid == 0 && out_size > Q_ELEMS)
            out[Q_ELEMS] = 1.25f * v / (float)Q_ELEMS;   // q_latent + 0.25*e_latent
    }
    __syncthreads();
    float p = (float)g_hist[tid] / (float)N_TOT;
    float t = -p * logf(p + 1e-10f);
    t = warpReduceSum(t);
    if ((tid & 31) == 0) red[tid >> 5] = t;
    __syncthreads();
    if (tid < 32) {
        float v = red[tid];
        v = warpReduceSum(v);
        if (tid == 0 && out_size > Q_ELEMS + 1)
            out[Q_ELEMS + 1] = expf(v);
    }
}

// ---------------------------------------------------------------------------
// 7) Indices as float (if output buffer includes them). grid=128, block=256
// ---------------------------------------------------------------------------
__global__ void idx_out_kernel(float* __restrict__ out) {
    int i = blockIdx.x * 256 + threadIdx.x;
    if (i < N_TOT) out[Q_ELEMS + 2 + i] = (float)g_idx[i];
}

// ---------------------------------------------------------------------------
extern "C" void kernel_launch(void* const* d_in, const int* in_sizes, int n_in,
                              void* d_out, int out_size) {
    const float* inputs = (const float*)d_in[0];
    const float* emb    = (const float*)d_in[1];
    if (n_in >= 2 && in_sizes[0] == K_CODES * D_DIM && in_sizes[1] == Q_ELEMS) {
        const float* t = inputs; inputs = emb; emb = t;
    }
    float* out = (float*)d_out;

    const int smem_bytes = (256 * XS_PITCH) * 4          // xs
                         + (NC_CODES * ES_PITCH) * 4     // es (tf32)
                         + K_CODES * 4                   // en
                         + 128 * 4;                      // norms
    cudaFuncSetAttribute(argmin_mma_kernel,
                         cudaFuncAttributeMaxDynamicSharedMemorySize, smem_bytes);

    enorm_kernel<<<K_CODES, 256>>>(emb);
    argmin_mma_kernel<<<N_TOT / 128, 256, smem_bytes>>>(inputs, emb);
    rescore_kernel<<<N_TOT / 8, 256>>>(inputs, emb);
    zero_hist_kernel<<<4, 256>>>();
    gather_kernel<<<GATHER_BLOCKS, 256>>>(inputs, emb, out);
    hist_kernel<<<32, 256>>>();
    finalize_kernel<<<1, 1024>>>(out, out_size);
    if (out_size >= Q_ELEMS + 2 + N_TOT) {
        idx_out_kernel<<<128, 256>>>(out);
    }
}

// round 7
// speedup vs baseline: 2.0589x; 1.1584x over previous
#include <cuda_runtime.h>
#include <cuda_bf16.h>
#include <cstdint>

// Problem constants
#define N_TOT   32768
#define D_DIM   256
#define K_CODES 1024
#define Q_ELEMS 8388608
#define GATHER_BLOCKS 2048
#define TAU     6e-4f

// smem geometry (bytes)
#define XP      136                 // xs pitch in b16 (272 B -> bank stride 4)
#define EP      264                 // es pitch in b16 (528 B -> bank stride 4)
#define SO_XS   0
#define SO_ES   69632               // 256*136*2
#define SO_EN   137216              // + 128*264*2 = 67584
#define SO_NORM 141312              // + 1024*4
#define SMEM_TOTAL 141824           // + 128*4

// Device scratch
__device__ float          g_enorm[K_CODES];
__device__ __nv_bfloat16  g_eb16[K_CODES * D_DIM];
__device__ int            g_idx[N_TOT];
__device__ int            g_ncand[N_TOT];
__device__ float          g_cand_v[N_TOT][16];
__device__ int            g_cand_i[N_TOT][16];
__device__ float          g_partials[GATHER_BLOCKS];
__device__ int            g_hist[K_CODES];

__device__ __forceinline__ float warpReduceSum(float v) {
    #pragma unroll
    for (int o = 16; o > 0; o >>= 1) v += __shfl_down_sync(0xffffffffu, v, o);
    return v;
}
__device__ __forceinline__ uint32_t smem_u32(const void* p) {
    uint32_t a;
    asm("{ .reg .u64 t; cvta.to.shared.u64 t, %1; cvt.u32.u64 %0, t; }" : "=r"(a) : "l"(p));
    return a;
}
__device__ __forceinline__ uint32_t packbf(float lo, float hi) {
    return ((uint32_t)__bfloat16_as_ushort(__float2bfloat16(hi)) << 16)
         |  (uint32_t)__bfloat16_as_ushort(__float2bfloat16(lo));
}

#define LDM_X4_T(r0,r1,r2,r3, a)                                               \
    asm volatile("ldmatrix.sync.aligned.m8n8.x4.trans.shared.b16 {%0,%1,%2,%3}, [%4];" \
                 : "=r"(r0), "=r"(r1), "=r"(r2), "=r"(r3) : "r"(a))
#define LDM_X4(r0,r1,r2,r3, a)                                                 \
    asm volatile("ldmatrix.sync.aligned.m8n8.x4.shared.b16 {%0,%1,%2,%3}, [%4];" \
                 : "=r"(r0), "=r"(r1), "=r"(r2), "=r"(r3) : "r"(a))
#define MMA_BF16(c0,c1,c2,c3, a0,a1,a2,a3, b0,b1)                              \
    asm volatile("mma.sync.aligned.m16n8k16.row.col.f32.bf16.bf16.f32 "        \
                 "{%0,%1,%2,%3},{%4,%5,%6,%7},{%8,%9},{%0,%1,%2,%3};"          \
                 : "+f"(c0), "+f"(c1), "+f"(c2), "+f"(c3)                      \
                 : "r"(a0), "r"(a1), "r"(a2), "r"(a3), "r"(b0), "r"(b1))

__device__ __forceinline__ void ins4(float v, int k, float bv[4], int bi[4]) {
    if (v < bv[3] || (v == bv[3] && k < bi[3])) {
        bv[3] = v; bi[3] = k;
        #pragma unroll
        for (int t = 3; t > 0; t--) {
            if (bv[t] < bv[t-1] || (bv[t] == bv[t-1] && bi[t] < bi[t-1])) {
                float tv = bv[t]; bv[t] = bv[t-1]; bv[t-1] = tv;
                int   ti = bi[t]; bi[t] = bi[t-1]; bi[t-1] = ti;
            }
        }
    }
}

// ---------------------------------------------------------------------------
// 1) ||e_k||^2. grid=1024, block=256
// ---------------------------------------------------------------------------
__global__ void enorm_kernel(const float* __restrict__ emb) {
    __shared__ float red[8];
    int k = blockIdx.x;
    float v = emb[k * D_DIM + threadIdx.x];
    float s = v * v;
    s = warpReduceSum(s);
    if ((threadIdx.x & 31) == 0) red[threadIdx.x >> 5] = s;
    __syncthreads();
    if (threadIdx.x < 8) {
        float t = red[threadIdx.x];
        #pragma unroll
        for (int o = 4; o > 0; o >>= 1) t += __shfl_down_sync(0xffu, t, o);
        if (threadIdx.x == 0) g_enorm[k] = t;
    }
}

// 1b) emb -> bf16 global (+ zero hist in first blocks). grid=256, block=256
__global__ void embconv_kernel(const float* __restrict__ emb) {
    int i = blockIdx.x * 256 + threadIdx.x;
    float4 t = ((const float4*)emb)[i];
    uint2 o;
    o.x = packbf(t.x, t.y);
    o.y = packbf(t.z, t.w);
    ((uint2*)g_eb16)[i] = o;
    if (i < K_CODES) g_hist[i] = 0;
}

// ---------------------------------------------------------------------------
// 2) bf16 mma.sync distance GEMM + best-4/lane + candidate emit.
//    CTA: 128 rows x 1024 codes (8 chunks of 128). 8 warps = 8 m16 row-groups.
//    grid=256, block=256, ~139KB dyn smem.
// ---------------------------------------------------------------------------
__global__ void __launch_bounds__(256, 1)
argmin_bf16_kernel(const float* __restrict__ x) {
    extern __shared__ __align__(16) char smem[];
    __nv_bfloat16* xs = (__nv_bfloat16*)(smem + SO_XS);   // [256 d][XP] (d-major)
    float* en_s  = (float*)(smem + SO_EN);
    float* norms = (float*)(smem + SO_NORM);

    const int tid  = threadIdx.x;
    const int lane = tid & 31;
    const int w    = tid >> 5;
    const int g4   = lane >> 2;          // groupID
    const int tg   = lane & 3;           // thread in group
    const int R    = w << 4;             // 16 rows per warp
    const int n0   = blockIdx.x << 7;
    const int b    = n0 >> 10;
    const int hw0  = n0 & 1023;
    const float* xb = x + ((size_t)b << 18) + hw0;

    // ---- fill xs: 16 iters, warp covers 2 d-lines x 128 rows
    #pragma unroll
    for (int i = 0; i < 16; i++) {
        int lin = i * 256 + tid;
        int d   = lin >> 4;
        int r8  = (lin & 15) << 3;
        float4 t0 = *(const float4*)(xb + ((size_t)d << 10) + r8);
        float4 t1 = *(const float4*)(xb + ((size_t)d << 10) + r8 + 4);
        uint4 u;
        u.x = packbf(t0.x, t0.y); u.y = packbf(t0.z, t0.w);
        u.z = packbf(t1.x, t1.y); u.w = packbf(t1.z, t1.w);
        *(uint4*)&xs[d * XP + r8] = u;
    }
    // ---- exact fp32 row norms (half-row per thread, partials in es scratch)
    {
        int row = tid & 127;
        int h   = tid >> 7;
        float a = 0.f;
        const float* p = xb + ((size_t)(h << 7) << 10) + row;
        #pragma unroll 8
        for (int d = 0; d < 128; d++) a = fmaf(p[(size_t)d << 10], p[(size_t)d << 10], a);
        ((float*)(smem + SO_ES))[tid] = a;
    }
    __syncthreads();
    if (tid < 128) norms[tid] = ((float*)(smem + SO_ES))[tid]
                              + ((float*)(smem + SO_ES))[tid + 128];
    for (int i = tid; i < K_CODES; i += 256) en_s[i] = g_enorm[i];
    __syncthreads();

    const float na0 = norms[R + g4];
    const float na1 = norms[R + g4 + 8];

    // per-lane ldmatrix base addresses
    const uint32_t xs_u = smem_u32(xs);
    const uint32_t es_u = smem_u32(smem + SO_ES);
    const int i8  = lane & 7;
    const int sel = lane >> 3;
    const uint32_t a_base = xs_u
        + (uint32_t)(((i8 + ((sel & 2) ? 8 : 0)) * XP + R + ((sel & 1) ? 8 : 0)) * 2);
    uint32_t b_base[4];
    #pragma unroll
    for (int p = 0; p < 4; p++)
        b_base[p] = es_u
            + (uint32_t)(((p * 16 + i8 + ((sel & 2) ? 8 : 0)) * EP) * 2
                         + ((sel & 1) ? 16 : 0));

    float bva[4], bvb[4]; int bia[4], bib[4];
    #pragma unroll
    for (int j = 0; j < 4; j++) {
        bva[j] = 3.4e38f; bvb[j] = 3.4e38f;
        bia[j] = 0x7fffffff; bib[j] = 0x7fffffff;
    }

    for (int chunk = 0; chunk < 8; chunk++) {
        __syncthreads();   // all warps done with previous es contents
        // stage 128 codes x 256 d bf16
        #pragma unroll
        for (int it = 0; it < 16; it++) {
            int lin = it * 256 + tid;              // 0..4095
            int c   = lin >> 5;                    // 0..127
            int d8  = (lin & 31) << 3;
            uint4 t = *(const uint4*)(g_eb16 + (((size_t)(chunk * 128 + c)) << 8) + d8);
            *(uint4*)(smem + SO_ES + (size_t)c * (EP * 2) + d8 * 2) = t;
        }
        __syncthreads();

        #pragma unroll
        for (int cb = 0; cb < 2; cb++) {
            float acc[8][4];
            #pragma unroll
            for (int j = 0; j < 8; j++)
                #pragma unroll
                for (int q = 0; q < 4; q++) acc[j][q] = 0.f;

            const uint32_t boff = (uint32_t)(cb * 64 * EP * 2);
            #pragma unroll
            for (int K = 0; K < 256; K += 16) {
                uint32_t a0, a1, a2, a3;
                LDM_X4_T(a0, a1, a2, a3, a_base + (uint32_t)(K * XP * 2));
                #pragma unroll
                for (int p = 0; p < 4; p++) {
                    uint32_t r0, r1, r2, r3;
                    LDM_X4(r0, r1, r2, r3, b_base[p] + boff + (uint32_t)(K * 2));
                    MMA_BF16(acc[2*p][0], acc[2*p][1], acc[2*p][2], acc[2*p][3],
                             a0, a1, a2, a3, r0, r1);
                    MMA_BF16(acc[2*p+1][0], acc[2*p+1][1], acc[2*p+1][2], acc[2*p+1][3],
                             a0, a1, a2, a3, r2, r3);
                }
            }
            // epilogue: dist + best-4 insert
            const int kb0 = chunk * 128 + cb * 64;
            #pragma unroll
            for (int j = 0; j < 8; j++) {
                int k0 = kb0 + 8 * j + 2 * tg;
                float e0 = en_s[k0], e1 = en_s[k0 + 1];
                ins4(fmaf(-2.f, acc[j][0], na0 + e0), k0,     bva, bia);
                ins4(fmaf(-2.f, acc[j][1], na0 + e1), k0 + 1, bva, bia);
                ins4(fmaf(-2.f, acc[j][2], na1 + e0), k0,     bvb, bib);
                ins4(fmaf(-2.f, acc[j][3], na1 + e1), k0 + 1, bvb, bib);
            }
        }
    }

    __syncthreads();   // es free -> candidate staging
    float* cand_v = (float*)(smem + SO_ES);           // [128][16]
    int*   cand_i = (int*)(smem + SO_ES + 8192);
    {
        int ra = R + g4, rb = R + g4 + 8;
        #pragma unroll
        for (int j = 0; j < 4; j++) {
            cand_v[ra * 16 + 4 * tg + j] = bva[j];
            cand_i[ra * 16 + 4 * tg + j] = bia[j];
            cand_v[rb * 16 + 4 * tg + j] = bvb[j];
            cand_i[rb * 16 + 4 * tg + j] = bib[j];
        }
    }
    __syncthreads();

    if (tid < 128) {
        int r = tid;
        float vm = cand_v[r * 16]; int im = cand_i[r * 16];
        #pragma unroll
        for (int j = 1; j < 16; j++) {
            float v = cand_v[r * 16 + j]; int k = cand_i[r * 16 + j];
            if (v < vm || (v == vm && k < im)) { vm = v; im = k; }
        }
        int cnt = 0;
        #pragma unroll
        for (int j = 0; j < 16; j++) cnt += (cand_v[r * 16 + j] <= vm + TAU);
        int n = n0 + r;
        if (cnt == 1) {
            g_idx[n] = im; g_ncand[n] = 1;
        } else {
            g_ncand[n] = 16;
            #pragma unroll
            for (int j = 0; j < 16; j++) {
                g_cand_v[n][j] = cand_v[r * 16 + j];
                g_cand_i[n][j] = cand_i[r * 16 + j];
            }
        }
    }
}

// ---------------------------------------------------------------------------
// 2b) Exact rescore of flagged rows (one warp per row). grid=1024, block=1024
// ---------------------------------------------------------------------------
__global__ void rescore_kernel(const float* __restrict__ x,
                               const float* __restrict__ emb) {
    int wid  = (blockIdx.x * blockDim.x + threadIdx.x) >> 5;
    int lane = threadIdx.x & 31;
    if (wid >= N_TOT) return;
    if (g_ncand[wid] == 1) return;

    int b = wid >> 10, hw = wid & 1023;
    const float* xr = x + ((size_t)b << 18) + hw;
    float xv[8];
    #pragma unroll
    for (int t = 0; t < 8; t++) xv[t] = xr[(size_t)(lane + (t << 5)) << 10];
    float a = 0.f;
    #pragma unroll
    for (int t = 0; t < 8; t++) a = fmaf(xv[t], xv[t], a);
    #pragma unroll
    for (int o = 16; o > 0; o >>= 1) a += __shfl_xor_sync(0xffffffffu, a, o);

    float cv[16]; int ci[16];
    #pragma unroll
    for (int j = 0; j < 16; j++) { cv[j] = g_cand_v[wid][j]; ci[j] = g_cand_i[wid][j]; }
    float vmin = cv[0];
    #pragma unroll
    for (int j = 1; j < 16; j++) vmin = fminf(vmin, cv[j]);

    float bestv = 3.4e38f; int besti = 0x7fffffff;
    for (int j = 0; j < 16; j++) {
        if (cv[j] > vmin + TAU) continue;
        int k = ci[j];
        const float* er = emb + ((size_t)k << 8);
        float d = 0.f;
        #pragma unroll
        for (int t = 0; t < 8; t++) d = fmaf(xv[t], er[lane + (t << 5)], d);
        #pragma unroll
        for (int o = 16; o > 0; o >>= 1) d += __shfl_xor_sync(0xffffffffu, d, o);
        float vv = fmaf(-2.f, d, a + g_enorm[k]);   // fl(fl(a+b) - 2*dot)
        if (vv < bestv || (vv == bestv && k < besti)) { bestv = vv; besti = k; }
    }
    if (lane == 0) g_idx[wid] = besti;
}

// ---------------------------------------------------------------------------
// 4) Gather (n,d4 mapping: 1x16B emb gather/lane, coalesced x/out) + SSE.
//    grid=2048, block=256, 4 iters.
// ---------------------------------------------------------------------------
__global__ void gather_kernel(const float* __restrict__ x,
                              const float* __restrict__ emb,
                              float* __restrict__ out) {
    float sse = 0.f;
    const int total = N_TOT * 64;   // (n, d4) units
    for (int T = blockIdx.x * blockDim.x + threadIdx.x; T < total;
         T += gridDim.x * blockDim.x) {
        int n  = T & 32767;
        int d4 = T >> 15;           // 0..63
        int b  = n >> 10;
        int hw = n & 1023;
        int idx = g_idx[n];
        float4 q = *(const float4*)(emb + ((size_t)idx << 8) + (d4 << 2));
        const float* xp = x + ((size_t)b << 18) + ((size_t)(d4 << 2) << 10) + hw;
        float* op = out + ((size_t)b << 18) + ((size_t)(d4 << 2) << 10) + hw;
        float qv[4] = {q.x, q.y, q.z, q.w};
        #pragma unroll
        for (int j = 0; j < 4; j++) {
            float xvj = xp[(size_t)j << 10];
            op[(size_t)j << 10] = qv[j];
            float dd = qv[j] - xvj;
            sse = fmaf(dd, dd, sse);
        }
    }
    __shared__ float red[8];
    sse = warpReduceSum(sse);
    if ((threadIdx.x & 31) == 0) red[threadIdx.x >> 5] = sse;
    __syncthreads();
    if (threadIdx.x < 8) {
        float v = red[threadIdx.x];
        #pragma unroll
        for (int o = 4; o > 0; o >>= 1) v += __shfl_down_sync(0xffu, v, o);
        if (threadIdx.x == 0) g_partials[blockIdx.x] = v;
    }
}

// ---------------------------------------------------------------------------
__global__ void hist_kernel() {
    __shared__ int sh[K_CODES];
    int tid = threadIdx.x;
    for (int i = tid; i < K_CODES; i += 256) sh[i] = 0;
    __syncthreads();
    int base = blockIdx.x * 1024;
    for (int i = tid; i < 1024; i += 256) atomicAdd(&sh[g_idx[base + i]], 1);
    __syncthreads();
    for (int i = tid; i < K_CODES; i += 256)
        if (sh[i]) atomicAdd(&g_hist[i], sh[i]);
}

__global__ void finalize_kernel(float* __restrict__ out, int out_size) {
    __shared__ float red[32];
    int tid = threadIdx.x;
    float s = 0.f;
    for (int i = tid; i < GATHER_BLOCKS; i += 1024) s += g_partials[i];
    s = warpReduceSum(s);
    if ((tid & 31) == 0) red[tid >> 5] = s;
    __syncthreads();
    if (tid < 32) {
        float v = red[tid];
        v = warpReduceSum(v);
        if (tid == 0 && out_size > Q_ELEMS)
            out[Q_ELEMS] = 1.25f * v / (float)Q_ELEMS;
    }
    __syncthreads();
    float p = (float)g_hist[tid] / (float)N_TOT;
    float t = -p * logf(p + 1e-10f);
    t = warpReduceSum(t);
    if ((tid & 31) == 0) red[tid >> 5] = t;
    __syncthreads();
    if (tid < 32) {
        float v = red[tid];
        v = warpReduceSum(v);
        if (tid == 0 && out_size > Q_ELEMS + 1)
            out[Q_ELEMS + 1] = expf(v);
    }
}

__global__ void idx_out_kernel(float* __restrict__ out) {
    int i = blockIdx.x * 256 + threadIdx.x;
    if (i < N_TOT) out[Q_ELEMS + 2 + i] = (float)g_idx[i];
}

// ---------------------------------------------------------------------------
extern "C" void kernel_launch(void* const* d_in, const int* in_sizes, int n_in,
                              void* d_out, int out_size) {
    const float* inputs = (const float*)d_in[0];
    const float* emb    = (const float*)d_in[1];
    if (n_in >= 2 && in_sizes[0] == K_CODES * D_DIM && in_sizes[1] == Q_ELEMS) {
        const float* t = inputs; inputs = emb; emb = t;
    }
    float* out = (float*)d_out;

    cudaFuncSetAttribute(argmin_bf16_kernel,
                         cudaFuncAttributeMaxDynamicSharedMemorySize, SMEM_TOTAL);

    enorm_kernel<<<K_CODES, 256>>>(emb);
    embconv_kernel<<<256, 256>>>(emb);
    argmin_bf16_kernel<<<N_TOT / 128, 256, SMEM_TOTAL>>>(inputs);
    rescore_kernel<<<1024, 1024>>>(inputs, emb);
    gather_kernel<<<GATHER_BLOCKS, 256>>>(inputs, emb, out);
    hist_kernel<<<32, 256>>>();
    finalize_kernel<<<1, 1024>>>(out, out_size);
    if (out_size >= Q_ELEMS + 2 + N_TOT) {
        idx_out_kernel<<<128, 256>>>(out);
    }
}

// round 8
// speedup vs baseline: 2.6302x; 1.2775x over previous
#include <cuda_runtime.h>
#include <cuda_bf16.h>
#include <cstdint>

// Problem constants
#define N_TOT   32768
#define D_DIM   256
#define K_CODES 1024
#define Q_ELEMS 8388608
#define GATHER_BLOCKS 2048
#define TAU     6e-4f

// smem geometry (bytes)
#define XP      136                  // xs pitch in b16
#define EP      264                  // es pitch in b16
#define SO_XS   0                    // 256*136*2 = 69632
#define SO_ES0  69632                // 128*264*2 = 67584
#define SO_ES1  137216
#define SO_EN   204800               // 1024 floats
#define SO_NORM 208896               // 128 floats
#define SO_FLAG 209408               // int cnt + 128 ints
#define SMEM_TOTAL 210048

// Device scratch
__device__ float          g_enorm[K_CODES];
__device__ __nv_bfloat16  g_eb16[K_CODES * D_DIM];
__device__ int            g_idx[N_TOT];
__device__ float          g_partials[GATHER_BLOCKS];
__device__ int            g_hist[K_CODES];

__device__ __forceinline__ float warpReduceSum(float v) {
    #pragma unroll
    for (int o = 16; o > 0; o >>= 1) v += __shfl_down_sync(0xffffffffu, v, o);
    return v;
}
__device__ __forceinline__ uint32_t smem_u32(const void* p) {
    uint32_t a;
    asm("{ .reg .u64 t; cvta.to.shared.u64 t, %1; cvt.u32.u64 %0, t; }" : "=r"(a) : "l"(p));
    return a;
}
__device__ __forceinline__ uint32_t packbf(float lo, float hi) {
    return ((uint32_t)__bfloat16_as_ushort(__float2bfloat16(hi)) << 16)
         |  (uint32_t)__bfloat16_as_ushort(__float2bfloat16(lo));
}

#define LDM_X4_T(r0,r1,r2,r3, a)                                               \
    asm volatile("ldmatrix.sync.aligned.m8n8.x4.trans.shared.b16 {%0,%1,%2,%3}, [%4];" \
                 : "=r"(r0), "=r"(r1), "=r"(r2), "=r"(r3) : "r"(a))
#define LDM_X4(r0,r1,r2,r3, a)                                                 \
    asm volatile("ldmatrix.sync.aligned.m8n8.x4.shared.b16 {%0,%1,%2,%3}, [%4];" \
                 : "=r"(r0), "=r"(r1), "=r"(r2), "=r"(r3) : "r"(a))
#define MMA_BF16(c0,c1,c2,c3, a0,a1,a2,a3, b0,b1)                              \
    asm volatile("mma.sync.aligned.m16n8k16.row.col.f32.bf16.bf16.f32 "        \
                 "{%0,%1,%2,%3},{%4,%5,%6,%7},{%8,%9},{%0,%1,%2,%3};"          \
                 : "+f"(c0), "+f"(c1), "+f"(c2), "+f"(c3)                      \
                 : "r"(a0), "r"(a1), "r"(a2), "r"(a3), "r"(b0), "r"(b1))
#define CP_ASYNC16(dst, src)                                                   \
    asm volatile("cp.async.cg.shared.global [%0], [%1], 16;" :: "r"(dst), "l"(src))
#define CP_COMMIT() asm volatile("cp.async.commit_group;" ::: "memory")
#define CP_WAIT0()  asm volatile("cp.async.wait_group 0;" ::: "memory")

__device__ __forceinline__ void ins3(float v, int k, float bv[3], int bi[3]) {
    if (v < bv[2] || (v == bv[2] && k < bi[2])) {
        bv[2] = v; bi[2] = k;
        #pragma unroll
        for (int t = 2; t > 0; t--) {
            if (bv[t] < bv[t-1] || (bv[t] == bv[t-1] && bi[t] < bi[t-1])) {
                float tv = bv[t]; bv[t] = bv[t-1]; bv[t-1] = tv;
                int   ti = bi[t]; bi[t] = bi[t-1]; bi[t-1] = ti;
            }
        }
    }
}

// ---------------------------------------------------------------------------
// 1) ||e_k||^2. grid=1024, block=256
// ---------------------------------------------------------------------------
__global__ void enorm_kernel(const float* __restrict__ emb) {
    __shared__ float red[8];
    int k = blockIdx.x;
    float v = emb[k * D_DIM + threadIdx.x];
    float s = v * v;
    s = warpReduceSum(s);
    if ((threadIdx.x & 31) == 0) red[threadIdx.x >> 5] = s;
    __syncthreads();
    if (threadIdx.x < 8) {
        float t = red[threadIdx.x];
        #pragma unroll
        for (int o = 4; o > 0; o >>= 1) t += __shfl_down_sync(0xffu, t, o);
        if (threadIdx.x == 0) g_enorm[k] = t;
    }
}

// 1b) emb -> bf16 global + zero hist. grid=256, block=256
__global__ void embconv_kernel(const float* __restrict__ emb) {
    int i = blockIdx.x * 256 + threadIdx.x;
    float4 t = ((const float4*)emb)[i];
    uint2 o;
    o.x = packbf(t.x, t.y);
    o.y = packbf(t.z, t.w);
    ((uint2*)g_eb16)[i] = o;
    if (i < K_CODES) g_hist[i] = 0;
}

// ---------------------------------------------------------------------------
// 2) bf16 mma.sync GEMM + best-3/lane + fused exact rescue.
//    CTA: 128 rows x 1024 codes (8 chunks of 128, double-buffered cp.async).
//    16 warps = 8 row-groups x 2 code-halves. grid=256, block=512.
// ---------------------------------------------------------------------------
__global__ void __launch_bounds__(512, 1)
argmin_bf16_kernel(const float* __restrict__ x, const float* __restrict__ embf) {
    extern __shared__ __align__(16) char smem[];
    __nv_bfloat16* xs = (__nv_bfloat16*)(smem + SO_XS);
    float* en_s  = (float*)(smem + SO_EN);
    float* norms = (float*)(smem + SO_NORM);
    int*   flagc = (int*)(smem + SO_FLAG);
    int*   flagr = flagc + 1;

    const int tid  = threadIdx.x;
    const int lane = tid & 31;
    const int w    = tid >> 5;           // 0..15
    const int rg   = w >> 1;             // row group 0..7
    const int chz  = w & 1;              // code half 0..1
    const int g4   = lane >> 2;
    const int tg   = lane & 3;
    const int R    = rg << 4;
    const int n0   = blockIdx.x << 7;
    const int b    = n0 >> 10;
    const int hw0  = n0 & 1023;
    const float* xb = x + ((size_t)b << 18) + hw0;

    const uint32_t es_base[2] = { smem_u32(smem + SO_ES0), smem_u32(smem + SO_ES1) };

    // ---- prologue: kick off chunk 0 staging via cp.async
    #pragma unroll
    for (int it = 0; it < 8; it++) {
        int lin = it * 512 + tid;        // 0..4095
        int c   = lin >> 5;
        int d8  = (lin & 31) << 3;
        CP_ASYNC16(es_base[0] + (uint32_t)(c * (EP * 2) + d8 * 2),
                   (const void*)(g_eb16 + ((size_t)c << 8) + d8));
    }
    CP_COMMIT();
    if (tid == 0) *flagc = 0;

    // ---- fill xs (bf16) ----
    #pragma unroll
    for (int i = 0; i < 8; i++) {
        int lin = i * 512 + tid;
        int d   = lin >> 4;
        int r8  = (lin & 15) << 3;
        float4 t0 = *(const float4*)(xb + ((size_t)d << 10) + r8);
        float4 t1 = *(const float4*)(xb + ((size_t)d << 10) + r8 + 4);
        uint4 u;
        u.x = packbf(t0.x, t0.y); u.y = packbf(t0.z, t0.w);
        u.z = packbf(t1.x, t1.y); u.w = packbf(t1.z, t1.w);
        *(uint4*)&xs[d * XP + r8] = u;
    }
    // ---- exact fp32 row norms: quarter-row per thread, scratch in es1
    {
        int row = tid & 127;
        int qd  = tid >> 7;              // 0..3
        float a = 0.f;
        const float* p = xb + ((size_t)(qd << 6) << 10) + row;
        #pragma unroll 8
        for (int d = 0; d < 64; d++) a = fmaf(p[(size_t)d << 10], p[(size_t)d << 10], a);
        ((float*)(smem + SO_ES1))[tid] = a;
    }
    for (int i = tid; i < K_CODES; i += 512) en_s[i] = g_enorm[i];
    __syncthreads();
    if (tid < 128) {
        const float* sc = (const float*)(smem + SO_ES1);
        norms[tid] = ((sc[tid] + sc[tid + 128]) + (sc[tid + 256] + sc[tid + 384]));
    }
    CP_WAIT0();
    __syncthreads();

    const float na0 = norms[R + g4];
    const float na1 = norms[R + g4 + 8];

    // per-lane ldmatrix addressing
    const uint32_t xs_u = smem_u32(xs);
    const int i8  = lane & 7;
    const int sel = lane >> 3;
    const uint32_t a_base = xs_u
        + (uint32_t)(((i8 + ((sel & 2) ? 8 : 0)) * XP + R + ((sel & 1) ? 8 : 0)) * 2);
    uint32_t b_off[4];
    #pragma unroll
    for (int p = 0; p < 4; p++)
        b_off[p] = (uint32_t)(((chz * 64 + p * 16 + i8 + ((sel & 2) ? 8 : 0)) * EP) * 2
                              + ((sel & 1) ? 16 : 0));

    float bva[3], bvb[3]; int bia[3], bib[3];
    #pragma unroll
    for (int j = 0; j < 3; j++) {
        bva[j] = 3.4e38f; bvb[j] = 3.4e38f;
        bia[j] = 0x7fffffff; bib[j] = 0x7fffffff;
    }

    for (int chunk = 0; chunk < 8; chunk++) {
        const uint32_t eb = es_base[chunk & 1];
        if (chunk < 7) {   // stage next chunk
            #pragma unroll
            for (int it = 0; it < 8; it++) {
                int lin = it * 512 + tid;
                int c   = lin >> 5;
                int d8  = (lin & 31) << 3;
                CP_ASYNC16(es_base[(chunk + 1) & 1] + (uint32_t)(c * (EP * 2) + d8 * 2),
                           (const void*)(g_eb16 + (((size_t)((chunk + 1) * 128 + c)) << 8) + d8));
            }
            CP_COMMIT();
        }

        float acc[8][4];
        #pragma unroll
        for (int j = 0; j < 8; j++)
            #pragma unroll
            for (int q = 0; q < 4; q++) acc[j][q] = 0.f;

        #pragma unroll
        for (int K = 0; K < 256; K += 16) {
            uint32_t a0, a1, a2, a3;
            LDM_X4_T(a0, a1, a2, a3, a_base + (uint32_t)(K * XP * 2));
            #pragma unroll
            for (int p = 0; p < 4; p++) {
                uint32_t r0, r1, r2, r3;
                LDM_X4(r0, r1, r2, r3, eb + b_off[p] + (uint32_t)(K * 2));
                MMA_BF16(acc[2*p][0], acc[2*p][1], acc[2*p][2], acc[2*p][3],
                         a0, a1, a2, a3, r0, r1);
                MMA_BF16(acc[2*p+1][0], acc[2*p+1][1], acc[2*p+1][2], acc[2*p+1][3],
                         a0, a1, a2, a3, r2, r3);
            }
        }
        // epilogue: dist + best-3 insert
        const int kb0 = chunk * 128 + chz * 64;
        #pragma unroll
        for (int j = 0; j < 8; j++) {
            int k0 = kb0 + (j >> 1) * 16 + (j & 1) * 8 + 2 * tg;
            float e0 = en_s[k0], e1 = en_s[k0 + 1];
            ins3(fmaf(-2.f, acc[j][0], na0 + e0), k0,     bva, bia);
            ins3(fmaf(-2.f, acc[j][1], na0 + e1), k0 + 1, bva, bia);
            ins3(fmaf(-2.f, acc[j][2], na1 + e0), k0,     bvb, bib);
            ins3(fmaf(-2.f, acc[j][3], na1 + e1), k0 + 1, bvb, bib);
        }
        if (chunk < 7) CP_WAIT0();
        __syncthreads();
    }

    // ---- candidate staging (alias es0; all MMA reads done) ----
    float* cand_v = (float*)(smem + SO_ES0);             // [128][24]
    int*   cand_i = (int*)(smem + SO_ES0 + 12288);
    {
        int ra = R + g4, rb = R + g4 + 8;
        int s0 = (chz * 4 + tg) * 3;
        #pragma unroll
        for (int j = 0; j < 3; j++) {
            cand_v[ra * 24 + s0 + j] = bva[j];
            cand_i[ra * 24 + s0 + j] = bia[j];
            cand_v[rb * 24 + s0 + j] = bvb[j];
            cand_i[rb * 24 + s0 + j] = bib[j];
        }
    }
    __syncthreads();

    // ---- decision per row ----
    if (tid < 128) {
        int r = tid;
        float vm = cand_v[r * 24]; int im = cand_i[r * 24];
        #pragma unroll
        for (int j = 1; j < 24; j++) {
            float v = cand_v[r * 24 + j]; int k = cand_i[r * 24 + j];
            if (v < vm || (v == vm && k < im)) { vm = v; im = k; }
        }
        int cnt = 0;
        #pragma unroll
        for (int j = 0; j < 24; j++) cnt += (cand_v[r * 24 + j] <= vm + TAU);
        if (cnt == 1) {
            g_idx[n0 + r] = im;
        } else {
            int slot = atomicAdd(flagc, 1);
            flagr[slot] = r;
        }
    }
    __syncthreads();

    // ---- fused exact rescue: warp per flagged row ----
    const int nflag = *flagc;
    for (int f = w; f < nflag; f += 16) {
        int r = flagr[f];
        const float* xr = xb + r;
        float xv[8];
        #pragma unroll
        for (int t = 0; t < 8; t++) xv[t] = xr[(size_t)(lane + (t << 5)) << 10];
        float a = norms[r];   // exact fp32 (translation-invariant vs reference)

        float vmin = cand_v[r * 24];
        #pragma unroll
        for (int j = 1; j < 24; j++) vmin = fminf(vmin, cand_v[r * 24 + j]);

        float bestv = 3.4e38f; int besti = 0x7fffffff;
        for (int j = 0; j < 24; j++) {
            float cv = cand_v[r * 24 + j];
            if (cv > vmin + TAU) continue;
            int k = cand_i[r * 24 + j];
            const float* er = embf + ((size_t)k << 8);
            float d = 0.f;
            #pragma unroll
            for (int t = 0; t < 8; t++) d = fmaf(xv[t], er[lane + (t << 5)], d);
            #pragma unroll
            for (int o = 16; o > 0; o >>= 1) d += __shfl_xor_sync(0xffffffffu, d, o);
            float vv = fmaf(-2.f, d, a + en_s[k]);   // fl(fl(a+b) - 2*dot)
            if (vv < bestv || (vv == bestv && k < besti)) { bestv = vv; besti = k; }
        }
        if (lane == 0) g_idx[n0 + r] = besti;
    }
}

// ---------------------------------------------------------------------------
// 4) Gather (n,d4 mapping) + SSE partials. grid=2048, block=256
// ---------------------------------------------------------------------------
__global__ void gather_kernel(const float* __restrict__ x,
                              const float* __restrict__ emb,
                              float* __restrict__ out) {
    float sse = 0.f;
    const int total = N_TOT * 64;
    for (int T = blockIdx.x * blockDim.x + threadIdx.x; T < total;
         T += gridDim.x * blockDim.x) {
        int n  = T & 32767;
        int d4 = T >> 15;
        int b  = n >> 10;
        int hw = n & 1023;
        int idx = g_idx[n];
        float4 q = *(const float4*)(emb + ((size_t)idx << 8) + (d4 << 2));
        const float* xp = x + ((size_t)b << 18) + ((size_t)(d4 << 2) << 10) + hw;
        float* op = out + ((size_t)b << 18) + ((size_t)(d4 << 2) << 10) + hw;
        float qv[4] = {q.x, q.y, q.z, q.w};
        #pragma unroll
        for (int j = 0; j < 4; j++) {
            float xvj = xp[(size_t)j << 10];
            op[(size_t)j << 10] = qv[j];
            float dd = qv[j] - xvj;
            sse = fmaf(dd, dd, sse);
        }
    }
    __shared__ float red[8];
    sse = warpReduceSum(sse);
    if ((threadIdx.x & 31) == 0) red[threadIdx.x >> 5] = sse;
    __syncthreads();
    if (threadIdx.x < 8) {
        float v = red[threadIdx.x];
        #pragma unroll
        for (int o = 4; o > 0; o >>= 1) v += __shfl_down_sync(0xffu, v, o);
        if (threadIdx.x == 0) g_partials[blockIdx.x] = v;
    }
}

// ---------------------------------------------------------------------------
__global__ void hist_kernel() {
    __shared__ int sh[K_CODES];
    int tid = threadIdx.x;
    for (int i = tid; i < K_CODES; i += 256) sh[i] = 0;
    __syncthreads();
    int base = blockIdx.x * 1024;
    for (int i = tid; i < 1024; i += 256) atomicAdd(&sh[g_idx[base + i]], 1);
    __syncthreads();
    for (int i = tid; i < K_CODES; i += 256)
        if (sh[i]) atomicAdd(&g_hist[i], sh[i]);
}

__global__ void finalize_kernel(float* __restrict__ out, int out_size) {
    __shared__ float red[32];
    int tid = threadIdx.x;
    float s = 0.f;
    for (int i = tid; i < GATHER_BLOCKS; i += 1024) s += g_partials[i];
    s = warpReduceSum(s);
    if ((tid & 31) == 0) red[tid >> 5] = s;
    __syncthreads();
    if (tid < 32) {
        float v = red[tid];
        v = warpReduceSum(v);
        if (tid == 0 && out_size > Q_ELEMS)
            out[Q_ELEMS] = 1.25f * v / (float)Q_ELEMS;
    }
    __syncthreads();
    float p = (float)g_hist[tid] / (float)N_TOT;
    float t = -p * logf(p + 1e-10f);
    t = warpReduceSum(t);
    if ((tid & 31) == 0) red[tid >> 5] = t;
    __syncthreads();
    if (tid < 32) {
        float v = red[tid];
        v = warpReduceSum(v);
        if (tid == 0 && out_size > Q_ELEMS + 1)
            out[Q_ELEMS + 1] = expf(v);
    }
}

__global__ void idx_out_kernel(float* __restrict__ out) {
    int i = blockIdx.x * 256 + threadIdx.x;
    if (i < N_TOT) out[Q_ELEMS + 2 + i] = (float)g_idx[i];
}

// ---------------------------------------------------------------------------
extern "C" void kernel_launch(void* const* d_in, const int* in_sizes, int n_in,
                              void* d_out, int out_size) {
    const float* inputs = (const float*)d_in[0];
    const float* emb    = (const float*)d_in[1];
    if (n_in >= 2 && in_sizes[0] == K_CODES * D_DIM && in_sizes[1] == Q_ELEMS) {
        const float* t = inputs; inputs = emb; emb = t;
    }
    float* out = (float*)d_out;

    cudaFuncSetAttribute(argmin_bf16_kernel,
                         cudaFuncAttributeMaxDynamicSharedMemorySize, SMEM_TOTAL);

    enorm_kernel<<<K_CODES, 256>>>(emb);
    embconv_kernel<<<256, 256>>>(emb);
    argmin_bf16_kernel<<<N_TOT / 128, 512, SMEM_TOTAL>>>(inputs, emb);
    gather_kernel<<<GATHER_BLOCKS, 256>>>(inputs, emb, out);
    hist_kernel<<<32, 256>>>();
    finalize_kernel<<<1, 1024>>>(out, out_size);
    if (out_size >= Q_ELEMS + 2 + N_TOT) {
        idx_out_kernel<<<128, 256>>>(out);
    }
}